// round 12
// baseline (speedup 1.0000x reference)
#include <cuda_runtime.h>
#include <cuda.h>
#include <cuda_fp16.h>
#include <cstdint>

// Problem constants
#define TOKENS 2048
#define HIDDEN 2048
#define INTER  5632
#define NEXP   8
#define TOPK   2
#define NPAIR  4096

#define MPAIR  16          // m-pair slots per expert (2x128 rows each)
#define BN1    64          // gemm1 n-tile
#define BN2    128         // gemm2 n-tile

// ---- tcgen05 config: fp16 K-major SW128, BK=64, NSTG=2, 2 CTAs/SM ----
#define BK_TC 64
#define NSTG  2
#define A_TILE_B  (256 * 128)            // 256 rows x 64k fp16 = 32 KB (one TMA box)
#define W1_TILE_B (64 * 128)             // 8 KB
#define W2_TILE_B (128 * 128)            // 16 KB
#define G1_STAGE  (A_TILE_B + 2 * W1_TILE_B)   // 48 KB
#define G2_STAGE  (A_TILE_B + W2_TILE_B)       // 48 KB
#define SMEM_TMEM 0
#define SMEM_CONS 16                      // consumed mbars (2 x 8B)
#define SMEM_FULL 32                      // TMA-full mbars (2 x 8B)
#define SMEM_DATA 1024
#define G1_SMEM (SMEM_DATA + NSTG * G1_STAGE)  // 99,328 -> 2 CTAs/SM
#define G2_SMEM (SMEM_DATA + NSTG * G2_STAGE)  // 99,328 -> 2 CTAs/SM

#define IDESC_G1 ((1u << 4) | ((BN1 / 8) << 17) | (8u << 24))   // M=128,N=64
#define IDESC_G2 ((1u << 4) | ((BN2 / 8) << 17) | (8u << 24))   // M=128,N=128

#define FSTR 36   // fallback smem stride

#if defined(__CUDA_ARCH__) && defined(__CUDA_ARCH_FEAT_SM103_ALL)
#define HAS_TCGEN05 1
#else
#define HAS_TCGEN05 0
#endif

// -------- persistent device scratch --------
__device__ int      d_cnt[NEXP];
__device__ int      d_off[NEXP];
__device__ int      d_tok[NPAIR];
__device__ int      d_pos[NPAIR];
// gathered x (expert-sorted, fp16 pairs) + pad rows (zeroed by xgather)
__device__ uint32_t d_xg[(size_t)(NPAIR + 256) * (HIDDEN / 2)];
__device__ uint32_t d_hbuf[(size_t)(NPAIR + 256) * (INTER / 2)];
__device__ float    d_ybuf[(size_t)NPAIR * HIDDEN];

// ---------------------------------------------------------------------------
// helpers
// ---------------------------------------------------------------------------
__device__ __forceinline__ uint32_t packh2(float lo, float hi) {
    __half2 h = __floats2half2_rn(lo, hi);
    return *reinterpret_cast<uint32_t*>(&h);
}
__device__ __forceinline__ void mma16816(float c[4], const uint32_t a[4],
                                         uint32_t b0, uint32_t b1) {
    asm volatile(
        "mma.sync.aligned.m16n8k16.row.col.f32.f16.f16.f32 "
        "{%0,%1,%2,%3}, {%4,%5,%6,%7}, {%8,%9}, {%0,%1,%2,%3};\n"
        : "+f"(c[0]), "+f"(c[1]), "+f"(c[2]), "+f"(c[3])
        : "r"(a[0]), "r"(a[1]), "r"(a[2]), "r"(a[3]), "r"(b0), "r"(b1));
}

#define STS128(a, q0, q1, q2, q3)                                                 \
    asm volatile("st.shared.v4.b32 [%0], {%1,%2,%3,%4};"                          \
        :: "r"(a), "r"(q0), "r"(q1), "r"(q2), "r"(q3) : "memory")

#if HAS_TCGEN05
__device__ __forceinline__ uint32_t smem_u32(const void* p) {
    uint32_t a;
    asm("{ .reg .u64 t; cvta.to.shared.u64 t, %1; cvt.u32.u64 %0, t; }" : "=r"(a) : "l"(p));
    return a;
}
__device__ __forceinline__ uint32_t swz128(uint32_t b) { return b ^ ((b >> 3) & 0x70); }
static __device__ __forceinline__ uint64_t make_desc(uint32_t addr) {
    // K-major SW128: layout=2, version=1, SBO=64, LBO=1
    return ((uint64_t)2 << 61) | ((uint64_t)1 << 46) | ((uint64_t)64 << 32) |
           ((uint64_t)1 << 16) | ((uint64_t)(addr >> 4) & 0x3FFF);
}

#define MBAR_INIT(a, c) \
    asm volatile("mbarrier.init.shared.b64 [%0], %1;" :: "r"(a), "r"(c) : "memory")
#define MBARRIER_EXPECT_TX(a, b) \
    asm volatile("mbarrier.arrive.expect_tx.shared.b64 _, [%0], %1;" :: "r"(a), "r"(b) : "memory")
#define MBAR_WAIT(a, ph) do {                                                     \
    uint32_t _m = (a), _p = (ph), _d;                                             \
    asm volatile("{\n\t.reg .pred p;\n\t"                                         \
        "mbarrier.try_wait.parity.acquire.cta.shared::cta.b64 p, [%1], %2;\n\t"   \
        "selp.b32 %0, 1, 0, p;\n\t}" : "=r"(_d) : "r"(_m), "r"(_p) : "memory");   \
    if (!_d) {                                                                     \
        asm volatile("{\n\t.reg .pred P1;\n\t"                                    \
        "W%=:\n\t"                                                                \
        "mbarrier.try_wait.parity.acquire.cta.shared::cta.b64 P1, [%0], %1, 0x989680;\n\t" \
        "@P1 bra.uni D%=;\n\t bra.uni W%=;\n\t D%=:\n\t}"                        \
        :: "r"(_m), "r"(_p) : "memory");                                          \
    } } while (0)

#define TMA_LOAD_2D(sm, mp, cx, cy, mb)                                           \
    asm volatile("cp.async.bulk.tensor.2d.shared::cta.global.tile.mbarrier::complete_tx::bytes " \
        "[%0], [%1, {%2, %3}], [%4];"                                             \
        :: "r"(sm), "l"(mp), "r"(cx), "r"(cy), "r"(mb) : "memory")

#define TC_ALLOC(sa, n)  asm volatile("tcgen05.alloc.cta_group::1.sync.aligned.shared::cta.b32 [%0], %1;" :: "r"(sa), "r"(n) : "memory")
#define TC_DEALLOC(t, n) asm volatile("tcgen05.dealloc.cta_group::1.sync.aligned.b32 %0, %1;" :: "r"(t), "r"(n))
#define TC_RELINQ()      asm volatile("tcgen05.relinquish_alloc_permit.cta_group::1.sync.aligned;")
#define TC_COMMIT(a)     asm volatile("tcgen05.commit.cta_group::1.mbarrier::arrive::one.shared::cluster.b64 [%0];" :: "r"(a) : "memory")
#define TC_FENCE_AFTER() asm volatile("tcgen05.fence::after_thread_sync;" ::: "memory")
#define TC_WAIT_LD()     asm volatile("tcgen05.wait::ld.sync.aligned;" ::: "memory")
#define FENCE_ASYNC()    asm volatile("fence.proxy.async.shared::cta;" ::: "memory")

__device__ __forceinline__ void mma_f16_ss(uint32_t d, uint64_t ad, uint64_t bd,
                                           uint32_t idesc, uint32_t en) {
    asm volatile(
        "{\n\t.reg .pred p;\n\t"
        "setp.ne.u32 p, %4, 0;\n\t"
        "tcgen05.mma.cta_group::1.kind::f16 [%0], %1, %2, %3, {%5, %5, %5, %5}, p;\n\t"
        "}" :: "r"(d), "l"(ad), "l"(bd), "r"(idesc), "r"(en), "r"(0u) : "memory");
}

#define LDTM_X32(r, a)                                                            \
    asm volatile("tcgen05.ld.sync.aligned.32x32b.x32.b32 "                        \
        "{%0,%1,%2,%3,%4,%5,%6,%7,%8,%9,%10,%11,%12,%13,%14,%15,"                 \
        "%16,%17,%18,%19,%20,%21,%22,%23,%24,%25,%26,%27,%28,%29,%30,%31}, [%32];"\
        : "=r"((r)[0]),"=r"((r)[1]),"=r"((r)[2]),"=r"((r)[3]),                    \
          "=r"((r)[4]),"=r"((r)[5]),"=r"((r)[6]),"=r"((r)[7]),                    \
          "=r"((r)[8]),"=r"((r)[9]),"=r"((r)[10]),"=r"((r)[11]),                  \
          "=r"((r)[12]),"=r"((r)[13]),"=r"((r)[14]),"=r"((r)[15]),                \
          "=r"((r)[16]),"=r"((r)[17]),"=r"((r)[18]),"=r"((r)[19]),                \
          "=r"((r)[20]),"=r"((r)[21]),"=r"((r)[22]),"=r"((r)[23]),                \
          "=r"((r)[24]),"=r"((r)[25]),"=r"((r)[26]),"=r"((r)[27]),                \
          "=r"((r)[28]),"=r"((r)[29]),"=r"((r)[30]),"=r"((r)[31]) : "r"(a))
#endif  // HAS_TCGEN05

// ---------------------------------------------------------------------------
// Routing
// ---------------------------------------------------------------------------
__global__ void route_kernel(const int* __restrict__ eidx) {
    __shared__ int s_cnt[NEXP], s_off[NEXP], s_cur[NEXP];
    int t = threadIdx.x;
    if (t < NEXP) s_cnt[t] = 0;
    __syncthreads();
    for (int p = t; p < NPAIR; p += blockDim.x) atomicAdd(&s_cnt[eidx[p]], 1);
    __syncthreads();
    if (t == 0) {
        int o = 0;
        for (int e = 0; e < NEXP; e++) { s_off[e] = o; s_cur[e] = o; o += s_cnt[e]; }
    }
    __syncthreads();
    for (int p = t; p < NPAIR; p += blockDim.x) {
        int pos = atomicAdd(&s_cur[eidx[p]], 1);
        d_tok[pos] = p >> 1;
        d_pos[p]   = pos;
    }
    if (t < NEXP) { d_cnt[t] = s_cnt[t]; d_off[t] = s_off[t]; }
}

// gather x rows into expert-sorted fp16 layout (+zero pad rows)
__global__ __launch_bounds__(256)
void xgather_kernel(const float* __restrict__ x) {
    const int slot = blockIdx.x;
    uint32_t* dst = d_xg + (size_t)slot * (HIDDEN / 2);
    if (slot < NPAIR) {
        const float* src = x + (size_t)d_tok[slot] * HIDDEN;
        for (int i = threadIdx.x; i < HIDDEN / 8; i += 256) {
            float4 v0 = *(const float4*)(src + i * 8);
            float4 v1 = *(const float4*)(src + i * 8 + 4);
            *(uint4*)(dst + i * 4) = make_uint4(packh2(v0.x, v0.y), packh2(v0.z, v0.w),
                                                packh2(v1.x, v1.y), packh2(v1.z, v1.w));
        }
    } else {
        for (int i = threadIdx.x; i < HIDDEN / 8; i += 256)
            *(uint4*)(dst + i * 4) = make_uint4(0, 0, 0, 0);
    }
}

// ---------------------------------------------------------------------------
// GEMM1: per CTA: 2 m-tiles (256 rows, TMA) x N=64; h = silu(gate)*up -> d_hbuf
// TMEM: gate0@0, up0@64, gate1@128, up1@192.
// ---------------------------------------------------------------------------
__global__ __launch_bounds__(256, 2)
void gemm1_kernel(const __grid_constant__ CUtensorMap tmap,
                  const float* __restrict__ w1g,
                  const float* __restrict__ w3g) {
    const int e    = blockIdx.x >> 4;
    const int cnt  = d_cnt[e];
    const int m0   = (blockIdx.x & 15) * 256;
    if (m0 >= cnt) return;
    const int n0   = blockIdx.y * BN1;
    const int off  = d_off[e];
    const int tid = threadIdx.x, wid = tid >> 5, lid = tid & 31;

    const float* w1b = w1g + (size_t)e * HIDDEN * INTER + n0;
    const float* w3b = w3g + (size_t)e * HIDDEN * INTER + n0;

#if HAS_TCGEN05
    extern __shared__ char smem[];
    const uint32_t sb = smem_u32(smem);

    if (wid == 0) TC_ALLOC(sb + SMEM_TMEM, 256);
    if (tid == 0)
        for (int s = 0; s < NSTG; s++) {
            MBAR_INIT(sb + SMEM_CONS + 8 * s, 1);
            MBAR_INIT(sb + SMEM_FULL + 8 * s, 1);
        }
    __syncthreads();
    uint32_t tmem;
    asm volatile("ld.shared.b32 %0, [%1];" : "=r"(tmem) : "r"(sb + SMEM_TMEM));
    if (wid == 0) TC_RELINQ();

    // W tasks (2 per matrix): t -> n = t&63, kb = t>>6 (0..7)
    const float *w1t[2], *w3t[2]; uint32_t w_sw[2];
#pragma unroll
    for (int i = 0; i < 2; i++) {
        int t = tid + i * 256, n = t & 63, kb = t >> 6;
        w1t[i] = w1b + (size_t)(kb * 8) * INTER + n;
        w3t[i] = w3b + (size_t)(kb * 8) * INTER + n;
        w_sw[i] = swz128((uint32_t)(n * 128 + kb * 16));
    }

    uint32_t w1pf[8], w3pf[8];
    auto prefetch = [&](int k0) {
#pragma unroll
        for (int i = 0; i < 2; i++) {
            const float* p1 = w1t[i] + (size_t)k0 * INTER;
            const float* p3 = w3t[i] + (size_t)k0 * INTER;
            float t1[8], t3[8];
#pragma unroll
            for (int j = 0; j < 8; j++) {
                t1[j] = p1[(size_t)j * INTER];
                t3[j] = p3[(size_t)j * INTER];
            }
#pragma unroll
            for (int j = 0; j < 4; j++) {
                w1pf[4*i+j] = packh2(t1[2*j], t1[2*j+1]);
                w3pf[4*i+j] = packh2(t3[2*j], t3[2*j+1]);
            }
        }
    };

    prefetch(0);
    const int NC = HIDDEN / BK_TC;   // 32
    for (int c = 0; c < NC; c++) {
        const int s = c & (NSTG - 1);
        if (c >= NSTG) MBAR_WAIT(sb + SMEM_CONS + 8 * s, ((c >> 1) - 1) & 1);

        const uint32_t stg = sb + SMEM_DATA + s * G1_STAGE;
        if (tid == 0) {                                    // A via TMA (async)
            MBARRIER_EXPECT_TX(sb + SMEM_FULL + 8 * s, A_TILE_B);
            TMA_LOAD_2D(stg, &tmap, c * BK_TC, off + m0, sb + SMEM_FULL + 8 * s);
        }
#pragma unroll
        for (int i = 0; i < 2; i++) {                      // W via SIMT fill
            STS128(stg + A_TILE_B + w_sw[i], w1pf[4*i], w1pf[4*i+1], w1pf[4*i+2], w1pf[4*i+3]);
            STS128(stg + A_TILE_B + W1_TILE_B + w_sw[i], w3pf[4*i], w3pf[4*i+1], w3pf[4*i+2], w3pf[4*i+3]);
        }
        __syncthreads();

        if (tid == 0) {
            MBAR_WAIT(sb + SMEM_FULL + 8 * s, (c >> 1) & 1);
            FENCE_ASYNC();
            uint64_t b1 = make_desc(stg + A_TILE_B);
            uint64_t b3 = make_desc(stg + A_TILE_B + W1_TILE_B);
#pragma unroll
            for (int mt = 0; mt < 2; mt++) {
                uint64_t ad = make_desc(stg + mt * (128 * 128));
#pragma unroll
                for (int ks = 0; ks < 4; ks++) {
                    uint32_t en = (c > 0 || ks > 0) ? 1u : 0u;
                    mma_f16_ss(tmem + mt * 128,      ad + ks * 2, b1 + ks * 2, IDESC_G1, en);
                    mma_f16_ss(tmem + mt * 128 + 64, ad + ks * 2, b3 + ks * 2, IDESC_G1, en);
                }
            }
            TC_COMMIT(sb + SMEM_CONS + 8 * s);
        }
        if (c + 1 < NC) prefetch((c + 1) * BK_TC);
    }

    MBAR_WAIT(sb + SMEM_CONS + 8 * ((NC - 1) & (NSTG - 1)), ((NC - 1) >> 1) & 1);
    TC_FENCE_AFTER();
    {
        const int mt = wid >> 2;
        const int mr = (wid & 3) * 32 + lid;
        const int r  = m0 + mt * 128 + mr;
        const bool ok = r < cnt;
        uint32_t* hrow = d_hbuf + (size_t)(off + r) * (INTER / 2) + n0 / 2;
        const uint32_t tb = tmem + mt * 128;
#pragma unroll
        for (int cc = 0; cc < 2; cc++) {
            const int cb = cc * 32;
            uint32_t gr[32], ur[32];
            LDTM_X32(gr, tb + cb);
            LDTM_X32(ur, tb + 64 + cb);
            TC_WAIT_LD();
            if (ok) {
                uint32_t hw[16];
#pragma unroll
                for (int j = 0; j < 16; j++) {
                    float g0 = __uint_as_float(gr[2*j]);
                    float g1 = __uint_as_float(gr[2*j+1]);
                    float h0 = g0 / (1.f + __expf(-g0)) * __uint_as_float(ur[2*j]);
                    float h1 = g1 / (1.f + __expf(-g1)) * __uint_as_float(ur[2*j+1]);
                    hw[j] = packh2(h0, h1);
                }
#pragma unroll
                for (int j = 0; j < 16; j += 4)
                    *(uint4*)(hrow + cb/2 + j) = make_uint4(hw[j], hw[j+1], hw[j+2], hw[j+3]);
            }
        }
    }
    __syncthreads();
    if (wid == 0) TC_DEALLOC(tmem, 256);

#else
    // ======= fallback: single-buffered mma.sync, 2 m-tiles sequential =======
    extern __shared__ uint32_t smw[];
    uint32_t* As  = smw;
    uint32_t* W1s = As + 128 * FSTR;
    uint32_t* W3s = W1s + 64 * FSTR;
    const int g = lid >> 2, tg = lid & 3;
    const int rg = (wid >> 1) * 32, cg = (wid & 1) * 32;

    for (int mt = 0; mt < 2; mt++) {
        const int mb = m0 + mt * 128;
        if (mb >= cnt) break;
        float gacc[2][4][4], uacc[2][4][4];
#pragma unroll
        for (int mi = 0; mi < 2; mi++)
#pragma unroll
            for (int ni = 0; ni < 4; ni++)
#pragma unroll
                for (int r = 0; r < 4; r++) { gacc[mi][ni][r] = 0.f; uacc[mi][ni][r] = 0.f; }

        for (int c = 0; c < HIDDEN / BK_TC; c++) {
            const int k0 = c * BK_TC;
#pragma unroll
            for (int i = 0; i < 2; i++) {
                int t = tid + i * 256, m = t >> 3, kb = t & 7;
                uint4 v = *(const uint4*)(d_xg + (size_t)(off + mb + m) * (HIDDEN/2) + k0/2 + kb * 4);
                uint32_t* p = &As[m * FSTR + kb * 4];
                p[0] = v.x; p[1] = v.y; p[2] = v.z; p[3] = v.w;
            }
#pragma unroll
            for (int i = 0; i < 2; i++) {
                int t = tid + i * 256, n = t & 63, kp = t >> 6;
                const float* p1 = w1b + (size_t)(k0 + kp * 8) * INTER + n;
                const float* p3 = w3b + (size_t)(k0 + kp * 8) * INTER + n;
#pragma unroll
                for (int j = 0; j < 4; j++) {
                    W1s[n * FSTR + kp * 4 + j] = packh2(p1[(2*j)*INTER], p1[(2*j+1)*INTER]);
                    W3s[n * FSTR + kp * 4 + j] = packh2(p3[(2*j)*INTER], p3[(2*j+1)*INTER]);
                }
            }
            __syncthreads();
#pragma unroll
            for (int kk = 0; kk < 4; kk++) {
                const int ko = kk * 8;
                uint32_t a[2][4];
#pragma unroll
                for (int mi = 0; mi < 2; mi++) {
                    int rb = rg + mi * 16;
                    a[mi][0] = As[(rb + g)     * FSTR + ko + tg];
                    a[mi][1] = As[(rb + g + 8) * FSTR + ko + tg];
                    a[mi][2] = As[(rb + g)     * FSTR + ko + tg + 4];
                    a[mi][3] = As[(rb + g + 8) * FSTR + ko + tg + 4];
                }
#pragma unroll
                for (int ni = 0; ni < 4; ni++) {
                    int cb = cg + ni * 8;
                    uint32_t b0 = W1s[(cb + g) * FSTR + ko + tg];
                    uint32_t b1 = W1s[(cb + g) * FSTR + ko + tg + 4];
                    uint32_t c0 = W3s[(cb + g) * FSTR + ko + tg];
                    uint32_t c1 = W3s[(cb + g) * FSTR + ko + tg + 4];
                    mma16816(gacc[0][ni], a[0], b0, b1);
                    mma16816(gacc[1][ni], a[1], b0, b1);
                    mma16816(uacc[0][ni], a[0], c0, c1);
                    mma16816(uacc[1][ni], a[1], c0, c1);
                }
            }
            __syncthreads();
        }
#pragma unroll
        for (int mi = 0; mi < 2; mi++)
#pragma unroll
            for (int ni = 0; ni < 4; ni++) {
                int r0 = mb + rg + mi * 16 + g;
                int r1 = r0 + 8;
                int col = n0 + cg + ni * 8 + tg * 2;
                if (r0 < cnt) {
                    float g0 = gacc[mi][ni][0], g1 = gacc[mi][ni][1];
                    float h0 = g0 / (1.f + __expf(-g0)) * uacc[mi][ni][0];
                    float h1 = g1 / (1.f + __expf(-g1)) * uacc[mi][ni][1];
                    d_hbuf[((size_t)(off + r0) * INTER + col) >> 1] = packh2(h0, h1);
                }
                if (r1 < cnt) {
                    float g2 = gacc[mi][ni][2], g3 = gacc[mi][ni][3];
                    float h2 = g2 / (1.f + __expf(-g2)) * uacc[mi][ni][2];
                    float h3 = g3 / (1.f + __expf(-g3)) * uacc[mi][ni][3];
                    d_hbuf[((size_t)(off + r1) * INTER + col) >> 1] = packh2(h2, h3);
                }
            }
        __syncthreads();
    }
#endif
}

// ---------------------------------------------------------------------------
// GEMM2: per CTA: 2 m-tiles (256 rows, TMA) x N=128; y -> d_ybuf
// ---------------------------------------------------------------------------
__global__ __launch_bounds__(256, 2)
void gemm2_kernel(const __grid_constant__ CUtensorMap tmap,
                  const float* __restrict__ w2g) {
    const int e    = blockIdx.x >> 4;
    const int cnt  = d_cnt[e];
    const int m0   = (blockIdx.x & 15) * 256;
    if (m0 >= cnt) return;
    const int n0   = blockIdx.y * BN2;
    const int off  = d_off[e];
    const int tid = threadIdx.x, wid = tid >> 5, lid = tid & 31;

    const float* w2b = w2g + (size_t)e * INTER * HIDDEN + n0;

#if HAS_TCGEN05
    extern __shared__ char smem[];
    const uint32_t sb = smem_u32(smem);

    if (wid == 0) TC_ALLOC(sb + SMEM_TMEM, 256);
    if (tid == 0)
        for (int s = 0; s < NSTG; s++) {
            MBAR_INIT(sb + SMEM_CONS + 8 * s, 1);
            MBAR_INIT(sb + SMEM_FULL + 8 * s, 1);
        }
    __syncthreads();
    uint32_t tmem;
    asm volatile("ld.shared.b32 %0, [%1];" : "=r"(tmem) : "r"(sb + SMEM_TMEM));
    if (wid == 0) TC_RELINQ();

    // W tasks (4): n = t&127, kb = t>>7 (0..7)
    const float* w2t[4]; uint32_t w_sw[4];
#pragma unroll
    for (int i = 0; i < 4; i++) {
        int t = tid + i * 256, n = t & 127, kb = t >> 7;
        w2t[i] = w2b + (size_t)(kb * 8) * HIDDEN + n;
        w_sw[i] = swz128((uint32_t)(n * 128 + kb * 16));
    }

    uint32_t wpf[16];
    auto prefetch = [&](int c) {
        const int k0 = c * BK_TC;
#pragma unroll
        for (int i = 0; i < 4; i++) {
            const float* p = w2t[i] + (size_t)k0 * HIDDEN;
            float t2[8];
#pragma unroll
            for (int j = 0; j < 8; j++) t2[j] = p[(size_t)j * HIDDEN];
#pragma unroll
            for (int j = 0; j < 4; j++) wpf[4*i+j] = packh2(t2[2*j], t2[2*j+1]);
        }
    };

    prefetch(0);
    const int NC = INTER / BK_TC;   // 88
    for (int c = 0; c < NC; c++) {
        const int s = c & (NSTG - 1);
        if (c >= NSTG) MBAR_WAIT(sb + SMEM_CONS + 8 * s, ((c >> 1) - 1) & 1);

        const uint32_t stg = sb + SMEM_DATA + s * G2_STAGE;
        if (tid == 0) {
            MBARRIER_EXPECT_TX(sb + SMEM_FULL + 8 * s, A_TILE_B);
            TMA_LOAD_2D(stg, &tmap, c * BK_TC, off + m0, sb + SMEM_FULL + 8 * s);
        }
#pragma unroll
        for (int i = 0; i < 4; i++)
            STS128(stg + A_TILE_B + w_sw[i], wpf[4*i], wpf[4*i+1], wpf[4*i+2], wpf[4*i+3]);
        __syncthreads();

        if (tid == 0) {
            MBAR_WAIT(sb + SMEM_FULL + 8 * s, (c >> 1) & 1);
            FENCE_ASYNC();
            uint64_t bd = make_desc(stg + A_TILE_B);
#pragma unroll
            for (int mt = 0; mt < 2; mt++) {
                uint64_t ad = make_desc(stg + mt * (128 * 128));
#pragma unroll
                for (int ks = 0; ks < 4; ks++)
                    mma_f16_ss(tmem + mt * 128, ad + ks * 2, bd + ks * 2, IDESC_G2,
                               (c > 0 || ks > 0) ? 1u : 0u);
            }
            TC_COMMIT(sb + SMEM_CONS + 8 * s);
        }
        if (c + 1 < NC) prefetch(c + 1);
    }

    MBAR_WAIT(sb + SMEM_CONS + 8 * ((NC - 1) & (NSTG - 1)), ((NC - 1) >> 1) & 1);
    TC_FENCE_AFTER();
    {
        const int mt = wid >> 2;
        const int mr = (wid & 3) * 32 + lid;
        const int r  = m0 + mt * 128 + mr;
        const bool ok = r < cnt;
        float* yrow = d_ybuf + (size_t)(off + r) * HIDDEN + n0;
        const uint32_t tb = tmem + mt * 128;
#pragma unroll
        for (int cc = 0; cc < 4; cc++) {
            const int cb = cc * 32;
            uint32_t yr[32];
            LDTM_X32(yr, tb + cb);
            TC_WAIT_LD();
            if (ok) {
#pragma unroll
                for (int j = 0; j < 32; j += 4) {
                    float4 v;
                    v.x = __uint_as_float(yr[j]);   v.y = __uint_as_float(yr[j+1]);
                    v.z = __uint_as_float(yr[j+2]); v.w = __uint_as_float(yr[j+3]);
                    *(float4*)(yrow + cb + j) = v;
                }
            }
        }
    }
    __syncthreads();
    if (wid == 0) TC_DEALLOC(tmem, 256);

#else
    // ======= fallback: single-buffered mma.sync =======
    extern __shared__ uint32_t smw[];
    uint32_t* As = smw;
    uint32_t* Ws = As + 128 * FSTR;
    const int g = lid >> 2, tg = lid & 3;
    const int rg = (wid >> 2) * 64, cg = (wid & 3) * 32;

    for (int mt = 0; mt < 2; mt++) {
        const int mb = m0 + mt * 128;
        if (mb >= cnt) break;
        float acc[4][4][4];
#pragma unroll
        for (int mi = 0; mi < 4; mi++)
#pragma unroll
            for (int ni = 0; ni < 4; ni++)
#pragma unroll
                for (int r = 0; r < 4; r++) acc[mi][ni][r] = 0.f;

        for (int c = 0; c < INTER / BK_TC; c++) {
            const int k0 = c * BK_TC;
#pragma unroll
            for (int i = 0; i < 2; i++) {
                int t = tid + i * 256, m = t >> 3, kb = t & 7;
                uint4 v = *(const uint4*)(d_hbuf + (size_t)(off + mb + m) * (INTER/2)
                                          + k0/2 + kb * 4);
                uint32_t* p = &As[m * FSTR + kb * 4];
                p[0] = v.x; p[1] = v.y; p[2] = v.z; p[3] = v.w;
            }
#pragma unroll
            for (int i = 0; i < 4; i++) {
                int t = tid + i * 256, n = t & 127, kp = t >> 7;
                const float* p = w2b + (size_t)(k0 + kp * 8) * HIDDEN + n;
#pragma unroll
                for (int j = 0; j < 4; j++)
                    Ws[n * FSTR + kp * 4 + j] = packh2(p[(2*j)*HIDDEN], p[(2*j+1)*HIDDEN]);
            }
            __syncthreads();
#pragma unroll
            for (int kk = 0; kk < 4; kk++) {
                const int ko = kk * 8;
                uint32_t a[4][4];
#pragma unroll
                for (int mi = 0; mi < 4; mi++) {
                    int rb = rg + mi * 16;
                    a[mi][0] = As[(rb + g)     * FSTR + ko + tg];
                    a[mi][1] = As[(rb + g + 8) * FSTR + ko + tg];
                    a[mi][2] = As[(rb + g)     * FSTR + ko + tg + 4];
                    a[mi][3] = As[(rb + g + 8) * FSTR + ko + tg + 4];
                }
#pragma unroll
                for (int ni = 0; ni < 4; ni++) {
                    int cb = cg + ni * 8;
                    uint32_t b0 = Ws[(cb + g) * FSTR + ko + tg];
                    uint32_t b1 = Ws[(cb + g) * FSTR + ko + tg + 4];
#pragma unroll
                    for (int mi = 0; mi < 4; mi++)
                        mma16816(acc[mi][ni], a[mi], b0, b1);
                }
            }
            __syncthreads();
        }
#pragma unroll
        for (int mi = 0; mi < 4; mi++)
#pragma unroll
            for (int ni = 0; ni < 4; ni++) {
                int r0 = mb + rg + mi * 16 + g;
                int r1 = r0 + 8;
                int col = n0 + cg + ni * 8 + tg * 2;
                if (r0 < cnt)
                    *(float2*)(d_ybuf + (size_t)(off + r0) * HIDDEN + col) =
                        make_float2(acc[mi][ni][0], acc[mi][ni][1]);
                if (r1 < cnt)
                    *(float2*)(d_ybuf + (size_t)(off + r1) * HIDDEN + col) =
                        make_float2(acc[mi][ni][2], acc[mi][ni][3]);
            }
        __syncthreads();
    }
#endif
}

// ---------------------------------------------------------------------------
// Combine
// ---------------------------------------------------------------------------
__global__ __launch_bounds__(256)
void combine_kernel(const float* __restrict__ ew, float* __restrict__ out) {
    const int t = blockIdx.x;
    const int p0 = d_pos[2 * t], p1 = d_pos[2 * t + 1];
    const float w0 = ew[2 * t], w1 = ew[2 * t + 1];
    const float4* y0 = (const float4*)(d_ybuf + (size_t)p0 * HIDDEN);
    const float4* y1 = (const float4*)(d_ybuf + (size_t)p1 * HIDDEN);
    float4* o = (float4*)(out + (size_t)t * HIDDEN);
#pragma unroll
    for (int i = threadIdx.x; i < HIDDEN / 4; i += 256) {
        float4 a = y0[i], b = y1[i], r;
        r.x = w0 * a.x + w1 * b.x; r.y = w0 * a.y + w1 * b.y;
        r.z = w0 * a.z + w1 * b.z; r.w = w0 * a.w + w1 * b.w;
        o[i] = r;
    }
}

// ---------------------------------------------------------------------------
// launch — inputs: x, expert_weights, w1, w2, w3, expert_indices
// ---------------------------------------------------------------------------
typedef CUresult (CUDAAPI *EncodeTiledFn)(
    CUtensorMap*, CUtensorMapDataType, cuuint32_t, void*,
    const cuuint64_t*, const cuuint64_t*, const cuuint32_t*, const cuuint32_t*,
    CUtensorMapInterleave, CUtensorMapSwizzle, CUtensorMapL2promotion,
    CUtensorMapFloatOOBfill);

extern "C" void kernel_launch(void* const* d_in, const int* in_sizes, int n_in,
                              void* d_out, int out_size) {
    const float* x  = (const float*)d_in[0];
    const float* ew = (const float*)d_in[1];
    const float* w1 = (const float*)d_in[2];
    const float* w2 = (const float*)d_in[3];
    const float* w3 = (const float*)d_in[4];
    const int*   ei = (const int*)d_in[5];
    float* out = (float*)d_out;

    static int init_done = 0;
    static CUtensorMap map_a1, map_a2;
    if (!init_done) {
        cudaFuncSetAttribute(gemm1_kernel, cudaFuncAttributeMaxDynamicSharedMemorySize, G1_SMEM);
        cudaFuncSetAttribute(gemm2_kernel, cudaFuncAttributeMaxDynamicSharedMemorySize, G2_SMEM);

        void* fn = nullptr;
        cudaDriverEntryPointQueryResult qr;
        cudaGetDriverEntryPoint("cuTensorMapEncodeTiled", &fn, cudaEnableDefault, &qr);
        EncodeTiledFn enc = (EncodeTiledFn)fn;

        void *xg_ptr = nullptr, *hb_ptr = nullptr;
        cudaGetSymbolAddress(&xg_ptr, d_xg);
        cudaGetSymbolAddress(&hb_ptr, d_hbuf);

        {
            cuuint64_t dims[2] = {HIDDEN, NPAIR + 256};
            cuuint64_t str[1]  = {HIDDEN * 2};
            cuuint32_t box[2]  = {BK_TC, 256};
            cuuint32_t es[2]   = {1, 1};
            enc(&map_a1, CU_TENSOR_MAP_DATA_TYPE_FLOAT16, 2, xg_ptr, dims, str, box, es,
                CU_TENSOR_MAP_INTERLEAVE_NONE, CU_TENSOR_MAP_SWIZZLE_128B,
                CU_TENSOR_MAP_L2_PROMOTION_L2_128B, CU_TENSOR_MAP_FLOAT_OOB_FILL_NONE);
        }
        {
            cuuint64_t dims[2] = {INTER, NPAIR + 256};
            cuuint64_t str[1]  = {INTER * 2};
            cuuint32_t box[2]  = {BK_TC, 256};
            cuuint32_t es[2]   = {1, 1};
            enc(&map_a2, CU_TENSOR_MAP_DATA_TYPE_FLOAT16, 2, hb_ptr, dims, str, box, es,
                CU_TENSOR_MAP_INTERLEAVE_NONE, CU_TENSOR_MAP_SWIZZLE_128B,
                CU_TENSOR_MAP_L2_PROMOTION_L2_128B, CU_TENSOR_MAP_FLOAT_OOB_FILL_NONE);
        }
        init_done = 1;
    }

    route_kernel<<<1, 256>>>(ei);
    xgather_kernel<<<NPAIR + 256, 256>>>(x);

    dim3 g1(NEXP * MPAIR, INTER / BN1);   // 128 x 88
    gemm1_kernel<<<g1, 256, G1_SMEM>>>(map_a1, w1, w3);

    dim3 g2(NEXP * MPAIR, HIDDEN / BN2);  // 128 x 16
    gemm2_kernel<<<g2, 256, G2_SMEM>>>(map_a2, w2);

    combine_kernel<<<TOKENS, 256>>>(ew, out);
}